// round 12
// baseline (speedup 1.0000x reference)
#include <cuda_runtime.h>

typedef unsigned long long ull;

#define SEQ   1024
#define NBH   64
#define LOG2E 1.4426950408889634f

// rel_h / rel_w logit tables, pre-scaled by log2(e): [bh][s][k], k in 0..31
__device__ __align__(16) float g_relH[(size_t)NBH * SEQ * 32];
__device__ __align__(16) float g_relW[(size_t)NBH * SEQ * 32];
// per-row (maxH+maxW [log2 units], |q_row|); per-head max ||k||
__device__ __align__(16) float2 g_rowB[(size_t)NBH * SEQ];
__device__ float g_knorm[NBH];

// ---------- f32x2 helpers ----------
__device__ __forceinline__ ull pack2(float x, float y) {
    ull r; asm("mov.b64 %0, {%1,%2};" : "=l"(r) : "f"(x), "f"(y)); return r;
}
__device__ __forceinline__ void unpack2(ull p, float& x, float& y) {
    asm("mov.b64 {%0,%1}, %2;" : "=f"(x), "=f"(y) : "l"(p));
}
__device__ __forceinline__ void fma2(ull& d, ull a, ull b) {
    asm("fma.rn.f32x2 %0, %1, %2, %0;" : "+l"(d) : "l"(a), "l"(b));
}
__device__ __forceinline__ float ex2f(float x) {
    float r; asm("ex2.approx.f32 %0, %1;" : "=f"(r) : "f"(x)); return r;
}

// ---------- kernel K: per-head max ||k_row|| ----------
__global__ void __launch_bounds__(256) knorm_kernel(const float* __restrict__ k)
{
    __shared__ float red[256];
    const int tid = threadIdx.x;
    const int bh = blockIdx.x;
    const int b = bh >> 4, hd = bh & 15;
    const size_t base = (size_t)b * SEQ * 1024 + (size_t)hd * 64;

    float mx = 0.f;
    #pragma unroll
    for (int it = 0; it < 4; it++) {
        const int s = tid + it * 256;
        const float4* kr = (const float4*)(k + base + (size_t)s * 1024);
        float sum = 0.f;
        #pragma unroll
        for (int f = 0; f < 16; f++) {
            float4 x = kr[f];
            sum += x.x * x.x + x.y * x.y + x.z * x.z + x.w * x.w;
        }
        mx = fmaxf(mx, sum);
    }
    red[tid] = mx;
    __syncthreads();
    #pragma unroll
    for (int off = 128; off > 0; off >>= 1) {
        if (tid < off) red[tid] = fmaxf(red[tid], red[tid + off]);
        __syncthreads();
    }
    if (tid == 0) g_knorm[bh] = sqrtf(red[0]);
}

// ---------- kernel A: rel_h / rel_w precompute + row bounds ----------
__global__ void __launch_bounds__(256) rel_kernel(
    const float* __restrict__ q,
    const float* __restrict__ rph,
    const float* __restrict__ rpw)
{
    __shared__ float sQ[32 * 68];
    __shared__ float sRh[32 * 68];
    __shared__ float sRw[63 * 68];

    const int tid = threadIdx.x;
    const int h  = blockIdx.x;
    const int bh = blockIdx.y;
    const int b = bh >> 4, hd = bh & 15;

    {
        const int w = tid >> 3, c0 = (tid & 7) * 8;
        const float4* src = (const float4*)(q + ((size_t)(b * SEQ + h * 32 + w) * 16 + hd) * 64 + c0);
        *(float4*)(sQ + w * 68 + c0)     = src[0];
        *(float4*)(sQ + w * 68 + c0 + 4) = src[1];
        const float4* hs = (const float4*)(rph + (size_t)(h + 31 - w) * 64 + c0);
        *(float4*)(sRh + w * 68 + c0)     = hs[0];
        *(float4*)(sRh + w * 68 + c0 + 4) = hs[1];
    }
    for (int i = tid; i < 63 * 16; i += 256) {
        int r = i >> 4, c = (i & 15) * 4;
        *(float4*)(sRw + r * 68 + c) = *(const float4*)(rpw + (size_t)r * 64 + c);
    }
    __syncthreads();

    const int wid = tid >> 5, lane = tid & 31;   // lane = k
    #pragma unroll
    for (int rr = 0; rr < 4; rr++) {
        const int w = wid * 4 + rr;
        const float4* qv = (const float4*)(sQ + w * 68);
        const float4* hv = (const float4*)(sRh + lane * 68);
        const float4* wv = (const float4*)(sRw + (w + 31 - lane) * 68);
        float ah = 0.f, aw = 0.f;
        #pragma unroll
        for (int f = 0; f < 16; f++) {
            float4 a = qv[f], x = hv[f], y = wv[f];
            ah += a.x * x.x + a.y * x.y + a.z * x.z + a.w * x.w;
            aw += a.x * y.x + a.y * y.y + a.z * y.z + a.w * y.w;
        }
        ah *= LOG2E;
        aw *= LOG2E;
        size_t o = ((size_t)bh * SEQ + h * 32 + w) * 32 + lane;
        g_relH[o] = ah;
        g_relW[o] = aw;

        float q0 = sQ[w * 68 + lane], q1 = sQ[w * 68 + lane + 32];
        float qn = q0 * q0 + q1 * q1;
        #pragma unroll
        for (int msk = 16; msk > 0; msk >>= 1) {
            ah = fmaxf(ah, __shfl_xor_sync(0xffffffffu, ah, msk));
            aw = fmaxf(aw, __shfl_xor_sync(0xffffffffu, aw, msk));
            qn += __shfl_xor_sync(0xffffffffu, qn, msk);
        }
        if (lane == 0)
            g_rowB[(size_t)bh * SEQ + h * 32 + w] = make_float2(ah + aw, sqrtf(qn));
    }
}

// ---------- kernel B: fp32 flash attention, m4 x n4 tiles, fixed-bound ------
// block 128 (tx 0..7, ty 0..15); thread tile 4 m-rows (mrow=4ty) x 4 n (tx+8j),
// d-cols = 4tx..4tx+3 and 4tx+32..4tx+35. S and O paired over m.
// KP stride 68: K[n][c] in QK, Pt[n][m] in PV. QK c-blocked by 4 (K float4).
#define QT_S 64
#define KP_S 68
#define VS_S 68
#define RL_S 34
#define BN   32

__global__ void __launch_bounds__(128, 4)
flash_kernel(const float* __restrict__ q, const float* __restrict__ k,
             const float* __restrict__ v, float* __restrict__ out)
{
    extern __shared__ float sm[];
    float* Qt = sm;                     // [64][64]  Qt[c][m] * 0.125*log2e
    float* KP = Qt + 64 * QT_S;         // [32][68]  K[n][c] in QK, Pt[n][m] in PV
    float* Vs = KP + BN * KP_S;         // [32][68]  V[n][d]
    float* rH = Vs + BN * VS_S;         // [64][34]
    float* rW = rH + 64 * RL_S;         // [64][34]

    const int tid = threadIdx.x;
    const int tx = tid & 7, ty = tid >> 3;
    const int mrow = ty << 2;
    const int m0 = blockIdx.x << 6;
    const int bh = blockIdx.y;
    const int b = bh >> 4, hd = bh & 15;

    const size_t hoff = (size_t)b * SEQ * 1024 + (size_t)hd * 64;
    const float* qh = q + hoff;
    const float* kh = k + hoff;
    const float* vh = v + hoff;
    float*       oh = out + hoff;

    // ---- load Q tile transposed (scaled) + rel tables ----
    {
        const int lr = tid & 63;
        const int lc = (tid >> 6) * 32;
        const float qs = 0.125f * LOG2E;
        const float4* src = (const float4*)(qh + (size_t)(m0 + lr) * 1024 + lc);
        #pragma unroll
        for (int f = 0; f < 8; f++) {
            float4 x = src[f];
            const int c = lc + 4 * f;
            Qt[(c + 0) * QT_S + lr] = x.x * qs;
            Qt[(c + 1) * QT_S + lr] = x.y * qs;
            Qt[(c + 2) * QT_S + lr] = x.z * qs;
            Qt[(c + 3) * QT_S + lr] = x.w * qs;
        }
        const float4* rh4 = (const float4*)(g_relH + ((size_t)bh * SEQ + m0) * 32);
        const float4* rw4 = (const float4*)(g_relW + ((size_t)bh * SEQ + m0) * 32);
        #pragma unroll
        for (int f = 0; f < 4; f++) {
            const int gi = tid + f * 128;         // float4 index within 64x32
            const int m = gi >> 3, c4 = (gi & 7) * 4;
            float4 xh = rh4[gi];
            float4 xw = rw4[gi];
            rH[m * RL_S + c4 + 0] = xh.x; rH[m * RL_S + c4 + 1] = xh.y;
            rH[m * RL_S + c4 + 2] = xh.z; rH[m * RL_S + c4 + 3] = xh.w;
            rW[m * RL_S + c4 + 0] = xw.x; rW[m * RL_S + c4 + 1] = xw.y;
            rW[m * RL_S + c4 + 2] = xw.z; rW[m * RL_S + c4 + 3] = xw.w;
        }
    }

    // per-row fixed softmax bound M and running sum (4 rows: mrow..mrow+3)
    float rowM[4], rowl[4];
    {
        const float kn = g_knorm[bh] * (0.125f * LOG2E);
        const float2* rb = g_rowB + (size_t)bh * SEQ + m0 + mrow;
        #pragma unroll
        for (int r = 0; r < 4; r++) {
            float2 x = rb[r];
            rowM[r] = x.x + x.y * kn;
            rowl[r] = 0.f;
        }
    }

    // O accumulator: Om[mpair i][u], ull lanes = rows (2i, 2i+1)
    // u 0..3 -> d = 4tx+u ; u 4..7 -> d = 4tx+32+(u-4)
    ull Om[2][8];
    #pragma unroll
    for (int i = 0; i < 2; i++)
        #pragma unroll
        for (int u = 0; u < 8; u++) Om[i][u] = 0ull;

    const int lrow = tid >> 2;            // loader row (0..31)
    const int lcol = (tid & 3) << 4;      // loader col base (0,16,32,48)

    for (int n0 = 0; n0 < SEQ; n0 += BN) {
        __syncthreads();   // prev PV done with KP/Vs (iter 0: Qt/rel stores)
        // ---- load K[n][c] + V[n][d] (stride 68, float4 stores) ----
        {
            const float4* ks  = (const float4*)(kh + (size_t)(n0 + lrow) * 1024 + lcol);
            const float4* vs4 = (const float4*)(vh + (size_t)(n0 + lrow) * 1024 + lcol);
            float4* kd = (float4*)(KP + lrow * KP_S + lcol);
            float4* vd = (float4*)(Vs + lrow * VS_S + lcol);
            #pragma unroll
            for (int f = 0; f < 4; f++) {
                kd[f] = ks[f];
                vd[f] = vs4[f];
            }
        }
        __syncthreads();

        // ---- S = Qs K^T : 4m x 4n, f32x2 paired over m, c-blocked by 4 ----
        ull Sa[2][4];
        #pragma unroll
        for (int i = 0; i < 2; i++)
            #pragma unroll
            for (int j = 0; j < 4; j++) Sa[i][j] = 0ull;

        #pragma unroll 4
        for (int c = 0; c < 64; c += 4) {
            float4 kv0 = *(const float4*)(KP + (tx + 0)  * KP_S + c);
            float4 kv1 = *(const float4*)(KP + (tx + 8)  * KP_S + c);
            float4 kv2 = *(const float4*)(KP + (tx + 16) * KP_S + c);
            float4 kv3 = *(const float4*)(KP + (tx + 24) * KP_S + c);
            ulonglong2 q0 = *(const ulonglong2*)(Qt + (c + 0) * QT_S + mrow);
            ulonglong2 q1 = *(const ulonglong2*)(Qt + (c + 1) * QT_S + mrow);
            ulonglong2 q2 = *(const ulonglong2*)(Qt + (c + 2) * QT_S + mrow);
            ulonglong2 q3 = *(const ulonglong2*)(Qt + (c + 3) * QT_S + mrow);

            ull b0, b1, b2, b3;
            b0 = pack2(kv0.x, kv0.x); b1 = pack2(kv1.x, kv1.x);
            b2 = pack2(kv2.x, kv2.x); b3 = pack2(kv3.x, kv3.x);
            fma2(Sa[0][0], q0.x, b0); fma2(Sa[1][0], q0.y, b0);
            fma2(Sa[0][1], q0.x, b1); fma2(Sa[1][1], q0.y, b1);
            fma2(Sa[0][2], q0.x, b2); fma2(Sa[1][2], q0.y, b2);
            fma2(Sa[0][3], q0.x, b3); fma2(Sa[1][3], q0.y, b3);
            b0 = pack2(kv0.y, kv0.y); b1 = pack2(kv1.y, kv1.y);
            b2 = pack2(kv2.y, kv2.y); b3 = pack2(kv3.y, kv3.y);
            fma2(Sa[0][0], q1.x, b0); fma2(Sa[1][0], q1.y, b0);
            fma2(Sa[0][1], q1.x, b1); fma2(Sa[1][1], q1.y, b1);
            fma2(Sa[0][2], q1.x, b2); fma2(Sa[1][2], q1.y, b2);
            fma2(Sa[0][3], q1.x, b3); fma2(Sa[1][3], q1.y, b3);
            b0 = pack2(kv0.z, kv0.z); b1 = pack2(kv1.z, kv1.z);
            b2 = pack2(kv2.z, kv2.z); b3 = pack2(kv3.z, kv3.z);
            fma2(Sa[0][0], q2.x, b0); fma2(Sa[1][0], q2.y, b0);
            fma2(Sa[0][1], q2.x, b1); fma2(Sa[1][1], q2.y, b1);
            fma2(Sa[0][2], q2.x, b2); fma2(Sa[1][2], q2.y, b2);
            fma2(Sa[0][3], q2.x, b3); fma2(Sa[1][3], q2.y, b3);
            b0 = pack2(kv0.w, kv0.w); b1 = pack2(kv1.w, kv1.w);
            b2 = pack2(kv2.w, kv2.w); b3 = pack2(kv3.w, kv3.w);
            fma2(Sa[0][0], q3.x, b0); fma2(Sa[1][0], q3.y, b0);
            fma2(Sa[0][1], q3.x, b1); fma2(Sa[1][1], q3.y, b1);
            fma2(Sa[0][2], q3.x, b2); fma2(Sa[1][2], q3.y, b2);
            fma2(Sa[0][3], q3.x, b3); fma2(Sa[1][3], q3.y, b3);
        }

        __syncthreads();   // all threads done reading KP as K

        // ---- softmax with fixed bound + Pt store (transposed, ull pairs) ----
        const int kh0 = n0 >> 5;
        #pragma unroll
        for (int i = 0; i < 2; i++) {
            float s0[4], s1[4];
            #pragma unroll
            for (int j = 0; j < 4; j++) unpack2(Sa[i][j], s0[j], s1[j]);
            const int R0 = mrow + 2 * i, R1 = R0 + 1;
            const float c0 = rH[R0 * RL_S + kh0] - rowM[2 * i];
            const float c1 = rH[R1 * RL_S + kh0] - rowM[2 * i + 1];
            float ps0 = 0.f, ps1 = 0.f;
            #pragma unroll
            for (int j = 0; j < 4; j++) {
                float p0 = ex2f(s0[j] + c0 + rW[R0 * RL_S + tx + 8 * j]);
                float p1 = ex2f(s1[j] + c1 + rW[R1 * RL_S + tx + 8 * j]);
                ps0 += p0; ps1 += p1;
                *(ull*)(KP + (tx + 8 * j) * KP_S + R0) = pack2(p0, p1);
            }
            rowl[2 * i]     += ps0;
            rowl[2 * i + 1] += ps1;
        }
        __syncthreads();

        // ---- O += P V : O paired over m, Pt broadcast reads, V float4 ----
        #pragma unroll 4
        for (int n = 0; n < BN; n++) {
            const float* vrow = Vs + n * VS_S + 4 * tx;
            float4 va = *(const float4*)vrow;
            float4 vb = *(const float4*)(vrow + 32);
            ulonglong2 pv = *(const ulonglong2*)(KP + n * KP_S + mrow);
            ull p0 = pv.x, p1 = pv.y;
            ull d0 = pack2(va.x, va.x), d1 = pack2(va.y, va.y);
            ull d2 = pack2(va.z, va.z), d3 = pack2(va.w, va.w);
            ull d4 = pack2(vb.x, vb.x), d5 = pack2(vb.y, vb.y);
            ull d6 = pack2(vb.z, vb.z), d7 = pack2(vb.w, vb.w);
            fma2(Om[0][0], p0, d0); fma2(Om[0][1], p0, d1);
            fma2(Om[0][2], p0, d2); fma2(Om[0][3], p0, d3);
            fma2(Om[0][4], p0, d4); fma2(Om[0][5], p0, d5);
            fma2(Om[0][6], p0, d6); fma2(Om[0][7], p0, d7);
            fma2(Om[1][0], p1, d0); fma2(Om[1][1], p1, d1);
            fma2(Om[1][2], p1, d2); fma2(Om[1][3], p1, d3);
            fma2(Om[1][4], p1, d4); fma2(Om[1][5], p1, d5);
            fma2(Om[1][6], p1, d6); fma2(Om[1][7], p1, d7);
        }
    }

    // ---- finalize ----
    #pragma unroll
    for (int r = 0; r < 4; r++) {
        float l = rowl[r];
        l += __shfl_xor_sync(0xffffffffu, l, 1);
        l += __shfl_xor_sync(0xffffffffu, l, 2);
        l += __shfl_xor_sync(0xffffffffu, l, 4);
        rowl[r] = __fdividef(1.0f, l);
    }
    #pragma unroll
    for (int i = 0; i < 2; i++) {
        const float inv0 = rowl[2 * i], inv1 = rowl[2 * i + 1];
        float oA[8], oB[8];
        #pragma unroll
        for (int u = 0; u < 8; u++) unpack2(Om[i][u], oA[u], oB[u]);
        float* op0 = oh + (size_t)(m0 + mrow + 2 * i) * 1024 + 4 * tx;
        float* op1 = op0 + 1024;
        *(float4*)op0        = make_float4(oA[0] * inv0, oA[1] * inv0, oA[2] * inv0, oA[3] * inv0);
        *(float4*)(op0 + 32) = make_float4(oA[4] * inv0, oA[5] * inv0, oA[6] * inv0, oA[7] * inv0);
        *(float4*)op1        = make_float4(oB[0] * inv1, oB[1] * inv1, oB[2] * inv1, oB[3] * inv1);
        *(float4*)(op1 + 32) = make_float4(oB[4] * inv1, oB[5] * inv1, oB[6] * inv1, oB[7] * inv1);
    }
}

extern "C" void kernel_launch(void* const* d_in, const int* in_sizes, int n_in,
                              void* d_out, int out_size)
{
    const float* q   = (const float*)d_in[0];
    const float* k   = (const float*)d_in[1];
    const float* v   = (const float*)d_in[2];
    const float* rph = (const float*)d_in[3];
    const float* rpw = (const float*)d_in[4];
    float* out = (float*)d_out;

    knorm_kernel<<<NBH, 256>>>(k);

    dim3 rg(32, 64);
    rel_kernel<<<rg, 256>>>(q, rph, rpw);

    const int smem = (64 * QT_S + BN * KP_S + BN * VS_S + 64 * RL_S * 2) * 4; // 51200 B
    cudaFuncSetAttribute(flash_kernel, cudaFuncAttributeMaxDynamicSharedMemorySize, smem);
    dim3 grid(SEQ / 64, NBH);
    flash_kernel<<<grid, 128, smem>>>(q, k, v, out);
}

// round 14
// speedup vs baseline: 1.4005x; 1.4005x over previous
#include <cuda_runtime.h>
#include <cuda_bf16.h>

typedef unsigned long long ull;
typedef unsigned int u32;

#define SEQ   1024
#define NBH   64
#define LOG2E 1.4426950408889634f

// rel_h / rel_w logit tables, pre-scaled by log2(e): [bh][s][k], k in 0..31
__device__ __align__(16) float g_relH[(size_t)NBH * SEQ * 32];
__device__ __align__(16) float g_relW[(size_t)NBH * SEQ * 32];
// per-row (maxH+maxW [log2 units], |q_row|); per-head max ||k||
__device__ __align__(16) float2 g_rowB[(size_t)NBH * SEQ];
__device__ float g_knorm[NBH];

// ---------------- helpers ----------------
__device__ __forceinline__ float ex2f(float x) {
    float r; asm("ex2.approx.f32 %0, %1;" : "=f"(r) : "f"(x)); return r;
}
__device__ __forceinline__ u32 smem_to_u32(const void* p) {
    u32 a;
    asm("{ .reg .u64 t; cvta.to.shared.u64 t, %1; cvt.u32.u64 %0, t; }" : "=r"(a) : "l"(p));
    return a;
}
#define SWZ(off) ((off) ^ (((off) >> 3) & 0x70))

__device__ __forceinline__ void ldsm_x4(u32& r0, u32& r1, u32& r2, u32& r3, u32 a) {
    asm volatile("ldmatrix.sync.aligned.m8n8.x4.shared.b16 {%0,%1,%2,%3}, [%4];"
                 : "=r"(r0), "=r"(r1), "=r"(r2), "=r"(r3) : "r"(a));
}
__device__ __forceinline__ void ldsm_x4_t(u32& r0, u32& r1, u32& r2, u32& r3, u32 a) {
    asm volatile("ldmatrix.sync.aligned.m8n8.x4.trans.shared.b16 {%0,%1,%2,%3}, [%4];"
                 : "=r"(r0), "=r"(r1), "=r"(r2), "=r"(r3) : "r"(a));
}
__device__ __forceinline__ void mma_bf16(float* c, const u32* a, u32 b0, u32 b1) {
    asm volatile("mma.sync.aligned.m16n8k16.row.col.f32.bf16.bf16.f32 "
                 "{%0,%1,%2,%3}, {%4,%5,%6,%7}, {%8,%9}, {%0,%1,%2,%3};"
                 : "+f"(c[0]), "+f"(c[1]), "+f"(c[2]), "+f"(c[3])
                 : "r"(a[0]), "r"(a[1]), "r"(a[2]), "r"(a[3]), "r"(b0), "r"(b1));
}
// split a pair of f32 into bf16x2 hi word + bf16x2 residual word
__device__ __forceinline__ void split2(float a, float b, u32& hi, u32& lo) {
    __nv_bfloat162 h = __floats2bfloat162_rn(a, b);
    hi = *(u32*)&h;
    float ra = a - __low2float(h);
    float rb = b - __high2float(h);
    __nv_bfloat162 l = __floats2bfloat162_rn(ra, rb);
    lo = *(u32*)&l;
}

// ---------- kernel K: per-head max ||k_row|| ----------
__global__ void __launch_bounds__(256) knorm_kernel(const float* __restrict__ k)
{
    __shared__ float red[256];
    const int tid = threadIdx.x;
    const int bh = blockIdx.x;
    const int b = bh >> 4, hd = bh & 15;
    const size_t base = (size_t)b * SEQ * 1024 + (size_t)hd * 64;

    float mx = 0.f;
    #pragma unroll
    for (int it = 0; it < 4; it++) {
        const int s = tid + it * 256;
        const float4* kr = (const float4*)(k + base + (size_t)s * 1024);
        float sum = 0.f;
        #pragma unroll
        for (int f = 0; f < 16; f++) {
            float4 x = kr[f];
            sum += x.x * x.x + x.y * x.y + x.z * x.z + x.w * x.w;
        }
        mx = fmaxf(mx, sum);
    }
    red[tid] = mx;
    __syncthreads();
    #pragma unroll
    for (int off = 128; off > 0; off >>= 1) {
        if (tid < off) red[tid] = fmaxf(red[tid], red[tid + off]);
        __syncthreads();
    }
    if (tid == 0) g_knorm[bh] = sqrtf(red[0]);
}

// ---------- kernel A: rel_h / rel_w precompute + row bounds ----------
__global__ void __launch_bounds__(256) rel_kernel(
    const float* __restrict__ q,
    const float* __restrict__ rph,
    const float* __restrict__ rpw)
{
    __shared__ float sQ[32 * 68];
    __shared__ float sRh[32 * 68];
    __shared__ float sRw[63 * 68];

    const int tid = threadIdx.x;
    const int h  = blockIdx.x;
    const int bh = blockIdx.y;
    const int b = bh >> 4, hd = bh & 15;

    {
        const int w = tid >> 3, c0 = (tid & 7) * 8;
        const float4* src = (const float4*)(q + ((size_t)(b * SEQ + h * 32 + w) * 16 + hd) * 64 + c0);
        *(float4*)(sQ + w * 68 + c0)     = src[0];
        *(float4*)(sQ + w * 68 + c0 + 4) = src[1];
        const float4* hs = (const float4*)(rph + (size_t)(h + 31 - w) * 64 + c0);
        *(float4*)(sRh + w * 68 + c0)     = hs[0];
        *(float4*)(sRh + w * 68 + c0 + 4) = hs[1];
    }
    for (int i = tid; i < 63 * 16; i += 256) {
        int r = i >> 4, c = (i & 15) * 4;
        *(float4*)(sRw + r * 68 + c) = *(const float4*)(rpw + (size_t)r * 64 + c);
    }
    __syncthreads();

    const int wid = tid >> 5, lane = tid & 31;   // lane = k
    #pragma unroll
    for (int rr = 0; rr < 4; rr++) {
        const int w = wid * 4 + rr;
        const float4* qv = (const float4*)(sQ + w * 68);
        const float4* hv = (const float4*)(sRh + lane * 68);
        const float4* wv = (const float4*)(sRw + (w + 31 - lane) * 68);
        float ah = 0.f, aw = 0.f;
        #pragma unroll
        for (int f = 0; f < 16; f++) {
            float4 a = qv[f], x = hv[f], y = wv[f];
            ah += a.x * x.x + a.y * x.y + a.z * x.z + a.w * x.w;
            aw += a.x * y.x + a.y * y.y + a.z * y.z + a.w * y.w;
        }
        ah *= LOG2E;
        aw *= LOG2E;
        size_t o = ((size_t)bh * SEQ + h * 32 + w) * 32 + lane;
        g_relH[o] = ah;
        g_relW[o] = aw;

        float q0 = sQ[w * 68 + lane], q1 = sQ[w * 68 + lane + 32];
        float qn = q0 * q0 + q1 * q1;
        #pragma unroll
        for (int msk = 16; msk > 0; msk >>= 1) {
            ah = fmaxf(ah, __shfl_xor_sync(0xffffffffu, ah, msk));
            aw = fmaxf(aw, __shfl_xor_sync(0xffffffffu, aw, msk));
            qn += __shfl_xor_sync(0xffffffffu, qn, msk);
        }
        if (lane == 0)
            g_rowB[(size_t)bh * SEQ + h * 32 + w] = make_float2(ah + aw, sqrtf(qn));
    }
}

// ---------- kernel B: mma.sync bf16 flash attention, fixed-bound softmax ----
// 128 threads / 4 warps, BM=64 (16 m/warp), BN=64. bf16 3-term splits.
// smem: bf16 tiles [64][64] SW128 (8KB each), rH table.
#define SM_QH 0
#define SM_QL 8192
#define SM_KH 16384
#define SM_KL 24576
#define SM_VH 32768
#define SM_VL 40960
#define SM_RH 49152
#define SM_TOT (SM_RH + 64 * 34 * 4)

__global__ void __launch_bounds__(128, 2)
flash_mma(const float* __restrict__ q, const float* __restrict__ k,
          const float* __restrict__ v, float* __restrict__ out)
{
    extern __shared__ __align__(1024) char smem[];
    float* rHs = (float*)(smem + SM_RH);
    const u32 sbase = smem_to_u32(smem);

    const int tid = threadIdx.x;
    const int lane = tid & 31, wid = tid >> 5;
    const int wm = wid * 16;
    const int l4 = lane >> 2;                 // 0..7  (fragment row)
    const int l2 = lane & 3;                  // fragment col pair
    const int m0 = blockIdx.x << 6;
    const int bh = blockIdx.y;
    const int b = bh >> 4, hd = bh & 15;

    const size_t hoff = (size_t)b * SEQ * 1024 + (size_t)hd * 64;
    const float* qg = q + hoff;
    const float* kg = k + hoff;
    const float* vg = v + hoff;
    float*       og = out + hoff;

    // ---- Q convert (scaled, split) + rH table ----
    {
        const int row = tid >> 1, cb = (tid & 1) * 32;
        const float qs = 0.125f * LOG2E;
        const float4* src = (const float4*)(qg + (size_t)(m0 + row) * 1024 + cb);
        #pragma unroll
        for (int f = 0; f < 8; f++) {
            float4 x = src[f];
            u32 h0, l0v, h1, l1v;
            split2(x.x * qs, x.y * qs, h0, l0v);
            split2(x.z * qs, x.w * qs, h1, l1v);
            const u32 bo = (u32)(row * 128 + 2 * (cb + 4 * f));
            const u32 o0 = SWZ(bo), o1 = SWZ(bo + 4);
            *(u32*)(smem + SM_QH + o0) = h0; *(u32*)(smem + SM_QH + o1) = h1;
            *(u32*)(smem + SM_QL + o0) = l0v; *(u32*)(smem + SM_QL + o1) = l1v;
        }
        const float4* rsrc = (const float4*)(g_relH + ((size_t)bh * SEQ + m0 + row) * 32 + (tid & 1) * 16);
        #pragma unroll
        for (int f = 0; f < 4; f++) {
            float4 x = rsrc[f];
            float* d = rHs + row * 34 + (tid & 1) * 16 + 4 * f;
            d[0] = x.x; d[1] = x.y; d[2] = x.z; d[3] = x.w;
        }
    }
    __syncthreads();

    // ---- Q A-fragments (registers, persistent) ----
    u32 aQh[4][4], aQl[4][4];
    {
        const int arow = wm + (lane & 15);
        #pragma unroll
        for (int ks = 0; ks < 4; ks++) {
            const u32 bo = (u32)(arow * 128 + 32 * ks + 16 * (lane >> 4));
            ldsm_x4(aQh[ks][0], aQh[ks][1], aQh[ks][2], aQh[ks][3], sbase + SM_QH + SWZ(bo));
            ldsm_x4(aQl[ks][0], aQl[ks][1], aQl[ks][2], aQl[ks][3], sbase + SM_QL + SWZ(bo));
        }
    }

    // ---- per-thread rel_w regs, row bound, row sums ----
    const int r0g = m0 + wm + l4, r1g = r0g + 8;
    float rw0[8], rw1[8], rowM0, rowM1, lsum0 = 0.f, lsum1 = 0.f;
    {
        const float* w0 = g_relW + ((size_t)bh * SEQ + r0g) * 32;
        const float* w1 = g_relW + ((size_t)bh * SEQ + r1g) * 32;
        #pragma unroll
        for (int j = 0; j < 4; j++) {
            rw0[2 * j]     = w0[8 * j + 2 * l2];
            rw0[2 * j + 1] = w0[8 * j + 2 * l2 + 1];
            rw1[2 * j]     = w1[8 * j + 2 * l2];
            rw1[2 * j + 1] = w1[8 * j + 2 * l2 + 1];
        }
        const float kn = g_knorm[bh] * (0.125f * LOG2E);
        float2 ra = g_rowB[(size_t)bh * SEQ + r0g];
        float2 rb = g_rowB[(size_t)bh * SEQ + r1g];
        rowM0 = ra.x + ra.y * kn;
        rowM1 = rb.x + rb.y * kn;
    }

    float o[8][4];
    #pragma unroll
    for (int i = 0; i < 8; i++)
        #pragma unroll
        for (int j = 0; j < 4; j++) o[i][j] = 0.f;

    for (int t = 0; t < 16; t++) {
        const int n0 = t * 64;
        __syncthreads();   // prior tile's ldmatrix done
        // ---- K,V convert + split into smem ----
        {
            const int row = tid >> 1, cb = (tid & 1) * 32;
            const float4* ksrc = (const float4*)(kg + (size_t)(n0 + row) * 1024 + cb);
            const float4* vsrc = (const float4*)(vg + (size_t)(n0 + row) * 1024 + cb);
            #pragma unroll
            for (int f = 0; f < 8; f++) {
                float4 x = ksrc[f];
                float4 y = vsrc[f];
                u32 h0, l0v, h1, l1v;
                const u32 bo = (u32)(row * 128 + 2 * (cb + 4 * f));
                const u32 o0 = SWZ(bo), o1 = SWZ(bo + 4);
                split2(x.x, x.y, h0, l0v);
                split2(x.z, x.w, h1, l1v);
                *(u32*)(smem + SM_KH + o0) = h0; *(u32*)(smem + SM_KH + o1) = h1;
                *(u32*)(smem + SM_KL + o0) = l0v; *(u32*)(smem + SM_KL + o1) = l1v;
                split2(y.x, y.y, h0, l0v);
                split2(y.z, y.w, h1, l1v);
                *(u32*)(smem + SM_VH + o0) = h0; *(u32*)(smem + SM_VH + o1) = h1;
                *(u32*)(smem + SM_VL + o0) = l0v; *(u32*)(smem + SM_VL + o1) = l1v;
            }
        }
        __syncthreads();

        // ---- S = Qh*Kh + Qh*Kl + Ql*Kh ----
        float s[8][4];
        #pragma unroll
        for (int i = 0; i < 8; i++)
            #pragma unroll
            for (int j = 0; j < 4; j++) s[i][j] = 0.f;

        #pragma unroll
        for (int ks = 0; ks < 4; ks++) {
            u32 bKh[8][2], bKl[8][2];
            const u32 colb = (u32)(32 * ks + 16 * ((lane >> 3) & 1));
            #pragma unroll
            for (int u = 0; u < 4; u++) {
                const u32 bo = (u32)((16 * u + ((lane >> 4) & 1) * 8 + (lane & 7)) * 128) + colb;
                ldsm_x4(bKh[2 * u][0], bKh[2 * u][1], bKh[2 * u + 1][0], bKh[2 * u + 1][1],
                        sbase + SM_KH + SWZ(bo));
                ldsm_x4(bKl[2 * u][0], bKl[2 * u][1], bKl[2 * u + 1][0], bKl[2 * u + 1][1],
                        sbase + SM_KL + SWZ(bo));
            }
            #pragma unroll
            for (int oc = 0; oc < 8; oc++) {
                mma_bf16(s[oc], aQh[ks], bKh[oc][0], bKh[oc][1]);
                mma_bf16(s[oc], aQh[ks], bKl[oc][0], bKl[oc][1]);
                mma_bf16(s[oc], aQl[ks], bKh[oc][0], bKh[oc][1]);
            }
        }

        // ---- softmax (fixed bound) + build P fragments in registers ----
        const int kh0 = 2 * t;
        const float rhA0 = rHs[(wm + l4) * 34 + kh0]     - rowM0;
        const float rhB0 = rHs[(wm + l4) * 34 + kh0 + 1] - rowM0;
        const float rhA1 = rHs[(wm + l4 + 8) * 34 + kh0]     - rowM1;
        const float rhB1 = rHs[(wm + l4 + 8) * 34 + kh0 + 1] - rowM1;

        u32 aPh[4][4], aPl[4][4];
        #pragma unroll
        for (int oc = 0; oc < 8; oc++) {
            const int j = oc & 3;
            const float c0 = (oc < 4) ? rhA0 : rhB0;
            const float c1 = (oc < 4) ? rhA1 : rhB1;
            float p0 = ex2f(s[oc][0] + rw0[2 * j]     + c0);
            float p1 = ex2f(s[oc][1] + rw0[2 * j + 1] + c0);
            float p2 = ex2f(s[oc][2] + rw1[2 * j]     + c1);
            float p3 = ex2f(s[oc][3] + rw1[2 * j + 1] + c1);
            lsum0 += p0 + p1;
            lsum1 += p2 + p3;
            u32 h01, l01, h23, l23;
            split2(p0, p1, h01, l01);
            split2(p2, p3, h23, l23);
            const int kf = oc >> 1, hi = (oc & 1) * 2;
            aPh[kf][hi] = h01; aPh[kf][hi + 1] = h23;
            aPl[kf][hi] = l01; aPl[kf][hi + 1] = l23;
        }

        // ---- O += Ph*Vh + Ph*Vl + Pl*Vh ----
        #pragma unroll
        for (int kf = 0; kf < 4; kf++) {
            u32 bVh[8][2], bVl[8][2];
            const int nb = 16 * kf;
            #pragma unroll
            for (int u = 0; u < 4; u++) {
                const u32 bo = (u32)((nb + ((lane >> 3) & 1) * 8 + (lane & 7)) * 128
                                     + 32 * u + 16 * ((lane >> 4) & 1));
                ldsm_x4_t(bVh[2 * u][0], bVh[2 * u][1], bVh[2 * u + 1][0], bVh[2 * u + 1][1],
                          sbase + SM_VH + SWZ(bo));
                ldsm_x4_t(bVl[2 * u][0], bVl[2 * u][1], bVl[2 * u + 1][0], bVl[2 * u + 1][1],
                          sbase + SM_VL + SWZ(bo));
            }
            #pragma unroll
            for (int du = 0; du < 8; du++) {
                mma_bf16(o[du], aPh[kf], bVh[du][0], bVh[du][1]);
                mma_bf16(o[du], aPh[kf], bVl[du][0], bVl[du][1]);
                mma_bf16(o[du], aPl[kf], bVh[du][0], bVh[du][1]);
            }
        }
    }

    // ---- finalize: reduce row sums over 4-lane groups, normalize, store ----
    lsum0 += __shfl_xor_sync(0xffffffffu, lsum0, 1);
    lsum0 += __shfl_xor_sync(0xffffffffu, lsum0, 2);
    lsum1 += __shfl_xor_sync(0xffffffffu, lsum1, 1);
    lsum1 += __shfl_xor_sync(0xffffffffu, lsum1, 2);
    const float inv0 = __fdividef(1.0f, lsum0);
    const float inv1 = __fdividef(1.0f, lsum1);

    float* op0 = og + (size_t)r0g * 1024;
    float* op1 = og + (size_t)r1g * 1024;
    #pragma unroll
    for (int du = 0; du < 8; du++) {
        const int d = 8 * du + 2 * l2;
        *(float2*)(op0 + d) = make_float2(o[du][0] * inv0, o[du][1] * inv0);
        *(float2*)(op1 + d) = make_float2(o[du][2] * inv1, o[du][3] * inv1);
    }
}

extern "C" void kernel_launch(void* const* d_in, const int* in_sizes, int n_in,
                              void* d_out, int out_size)
{
    const float* q   = (const float*)d_in[0];
    const float* k   = (const float*)d_in[1];
    const float* v   = (const float*)d_in[2];
    const float* rph = (const float*)d_in[3];
    const float* rpw = (const float*)d_in[4];
    float* out = (float*)d_out;

    knorm_kernel<<<NBH, 256>>>(k);

    dim3 rg(32, 64);
    rel_kernel<<<rg, 256>>>(q, rph, rpw);

    cudaFuncSetAttribute(flash_mma, cudaFuncAttributeMaxDynamicSharedMemorySize, SM_TOT);
    dim3 grid(SEQ / 64, NBH);
    flash_mma<<<grid, 128, SM_TOT>>>(q, k, v, out);
}

// round 15
// speedup vs baseline: 2.6342x; 1.8809x over previous
#include <cuda_runtime.h>
#include <cuda_bf16.h>

typedef unsigned long long ull;
typedef unsigned int u32;

#define SEQ   1024
#define NBH   64
#define LOG2E 1.4426950408889634f

// rel_h / rel_w logit tables, pre-scaled by log2(e): [bh][s][k], k in 0..31
__device__ __align__(16) float g_relH[(size_t)NBH * SEQ * 32];
__device__ __align__(16) float g_relW[(size_t)NBH * SEQ * 32];
// per-row (maxH+maxW [log2 units], |q_row|)
__device__ __align__(16) float2 g_rowB[(size_t)NBH * SEQ];
// per-head max ||k||^2 as float bits (atomicMax; zero-init; idempotent across replays)
__device__ int g_knormi[NBH];
// pre-converted bf16 hi/lo K and V: [bh][n][c] linear, 128B rows
__device__ __align__(16) __nv_bfloat16 g_KH[(size_t)NBH * SEQ * 64];
__device__ __align__(16) __nv_bfloat16 g_KL[(size_t)NBH * SEQ * 64];
__device__ __align__(16) __nv_bfloat16 g_VH[(size_t)NBH * SEQ * 64];
__device__ __align__(16) __nv_bfloat16 g_VL[(size_t)NBH * SEQ * 64];

// ---------------- helpers ----------------
__device__ __forceinline__ float ex2f(float x) {
    float r; asm("ex2.approx.f32 %0, %1;" : "=f"(r) : "f"(x)); return r;
}
__device__ __forceinline__ u32 smem_to_u32(const void* p) {
    u32 a;
    asm("{ .reg .u64 t; cvta.to.shared.u64 t, %1; cvt.u32.u64 %0, t; }" : "=r"(a) : "l"(p));
    return a;
}
#define SWZ(off) ((off) ^ (((off) >> 3) & 0x70))

__device__ __forceinline__ void ldsm_x4(u32& r0, u32& r1, u32& r2, u32& r3, u32 a) {
    asm volatile("ldmatrix.sync.aligned.m8n8.x4.shared.b16 {%0,%1,%2,%3}, [%4];"
                 : "=r"(r0), "=r"(r1), "=r"(r2), "=r"(r3) : "r"(a));
}
__device__ __forceinline__ void ldsm_x4_t(u32& r0, u32& r1, u32& r2, u32& r3, u32 a) {
    asm volatile("ldmatrix.sync.aligned.m8n8.x4.trans.shared.b16 {%0,%1,%2,%3}, [%4];"
                 : "=r"(r0), "=r"(r1), "=r"(r2), "=r"(r3) : "r"(a));
}
__device__ __forceinline__ void mma_bf16(float* c, const u32* a, u32 b0, u32 b1) {
    asm volatile("mma.sync.aligned.m16n8k16.row.col.f32.bf16.bf16.f32 "
                 "{%0,%1,%2,%3}, {%4,%5,%6,%7}, {%8,%9}, {%0,%1,%2,%3};"
                 : "+f"(c[0]), "+f"(c[1]), "+f"(c[2]), "+f"(c[3])
                 : "r"(a[0]), "r"(a[1]), "r"(a[2]), "r"(a[3]), "r"(b0), "r"(b1));
}
__device__ __forceinline__ void split2(float a, float b, u32& hi, u32& lo) {
    __nv_bfloat162 h = __floats2bfloat162_rn(a, b);
    hi = *(u32*)&h;
    float ra = a - __low2float(h);
    float rb = b - __high2float(h);
    __nv_bfloat162 l = __floats2bfloat162_rn(ra, rb);
    lo = *(u32*)&l;
}
__device__ __forceinline__ void cp16(u32 dst, const void* src) {
    asm volatile("cp.async.cg.shared.global [%0], [%1], 16;" :: "r"(dst), "l"(src) : "memory");
}
#define CP_COMMIT() asm volatile("cp.async.commit_group;" ::: "memory")
#define CP_WAIT(n)  asm volatile("cp.async.wait_group %0;" :: "n"(n) : "memory")

// ---------- kernel C: K/V pre-convert to bf16 hi/lo + per-head knorm ----------
// grid (16 tiles, 64 bh), 128 threads. thread: row=tid>>1, 32 cols.
__global__ void __launch_bounds__(128) kv_convert(const float* __restrict__ k,
                                                  const float* __restrict__ v)
{
    const int tid = threadIdx.x;
    const int bh = blockIdx.y;
    const int b = bh >> 4, hd = bh & 15;
    const int r = blockIdx.x * 64 + (tid >> 1);
    const int cb = (tid & 1) * 32;
    const size_t hoff = (size_t)b * SEQ * 1024 + (size_t)hd * 64;

    const float4* ks = (const float4*)(k + hoff + (size_t)r * 1024 + cb);
    const float4* vs = (const float4*)(v + hoff + (size_t)r * 1024 + cb);
    const size_t eb = (((size_t)bh * SEQ + r) * 64 + cb) >> 1;   // u32 index
    u32* dKH = (u32*)g_KH + eb;
    u32* dKL = (u32*)g_KL + eb;
    u32* dVH = (u32*)g_VH + eb;
    u32* dVL = (u32*)g_VL + eb;

    float ksum = 0.f;
    #pragma unroll
    for (int f = 0; f < 8; f++) {
        float4 x = ks[f];
        ksum += x.x * x.x + x.y * x.y + x.z * x.z + x.w * x.w;
        u32 h0, l0, h1, l1;
        split2(x.x, x.y, h0, l0);
        split2(x.z, x.w, h1, l1);
        dKH[2 * f] = h0; dKH[2 * f + 1] = h1;
        dKL[2 * f] = l0; dKL[2 * f + 1] = l1;
        float4 y = vs[f];
        split2(y.x, y.y, h0, l0);
        split2(y.z, y.w, h1, l1);
        dVH[2 * f] = h0; dVH[2 * f + 1] = h1;
        dVL[2 * f] = l0; dVL[2 * f + 1] = l1;
    }
    // full row norm^2 (combine column halves), then warp max over 16 rows
    ksum += __shfl_xor_sync(0xffffffffu, ksum, 1);
    #pragma unroll
    for (int m = 2; m <= 16; m <<= 1)
        ksum = fmaxf(ksum, __shfl_xor_sync(0xffffffffu, ksum, m));
    if ((tid & 31) == 0) atomicMax(&g_knormi[bh], __float_as_int(ksum));
}

// ---------- kernel A: rel_h / rel_w precompute + row bounds ----------
__global__ void __launch_bounds__(256) rel_kernel(
    const float* __restrict__ q,
    const float* __restrict__ rph,
    const float* __restrict__ rpw)
{
    __shared__ float sQ[32 * 68];
    __shared__ float sRh[32 * 68];
    __shared__ float sRw[63 * 68];

    const int tid = threadIdx.x;
    const int h  = blockIdx.x;
    const int bh = blockIdx.y;
    const int b = bh >> 4, hd = bh & 15;

    {
        const int w = tid >> 3, c0 = (tid & 7) * 8;
        const float4* src = (const float4*)(q + ((size_t)(b * SEQ + h * 32 + w) * 16 + hd) * 64 + c0);
        *(float4*)(sQ + w * 68 + c0)     = src[0];
        *(float4*)(sQ + w * 68 + c0 + 4) = src[1];
        const float4* hs = (const float4*)(rph + (size_t)(h + 31 - w) * 64 + c0);
        *(float4*)(sRh + w * 68 + c0)     = hs[0];
        *(float4*)(sRh + w * 68 + c0 + 4) = hs[1];
    }
    for (int i = tid; i < 63 * 16; i += 256) {
        int r = i >> 4, c = (i & 15) * 4;
        *(float4*)(sRw + r * 68 + c) = *(const float4*)(rpw + (size_t)r * 64 + c);
    }
    __syncthreads();

    const int wid = tid >> 5, lane = tid & 31;   // lane = k
    #pragma unroll
    for (int rr = 0; rr < 4; rr++) {
        const int w = wid * 4 + rr;
        const float4* qv = (const float4*)(sQ + w * 68);
        const float4* hv = (const float4*)(sRh + lane * 68);
        const float4* wv = (const float4*)(sRw + (w + 31 - lane) * 68);
        float ah = 0.f, aw = 0.f;
        #pragma unroll
        for (int f = 0; f < 16; f++) {
            float4 a = qv[f], x = hv[f], y = wv[f];
            ah += a.x * x.x + a.y * x.y + a.z * x.z + a.w * x.w;
            aw += a.x * y.x + a.y * y.y + a.z * y.z + a.w * y.w;
        }
        ah *= LOG2E;
        aw *= LOG2E;
        size_t o = ((size_t)bh * SEQ + h * 32 + w) * 32 + lane;
        g_relH[o] = ah;
        g_relW[o] = aw;

        float q0 = sQ[w * 68 + lane], q1 = sQ[w * 68 + lane + 32];
        float qn = q0 * q0 + q1 * q1;
        #pragma unroll
        for (int msk = 16; msk > 0; msk >>= 1) {
            ah = fmaxf(ah, __shfl_xor_sync(0xffffffffu, ah, msk));
            aw = fmaxf(aw, __shfl_xor_sync(0xffffffffu, aw, msk));
            qn += __shfl_xor_sync(0xffffffffu, qn, msk);
        }
        if (lane == 0)
            g_rowB[(size_t)bh * SEQ + h * 32 + w] = make_float2(ah + aw, sqrtf(qn));
    }
}

// ---------- kernel B: mma.sync bf16 flash attention, async staged K/V -------
// 128 threads / 4 warps, BM=64 (16 m/warp), BN=64. bf16 3-term splits.
// K/V tiles pre-converted; cp.async double-buffered into swizzled smem.
#define KV_BUF  32768       // KH+KL+VH+VL, 8KB each
#define SM_QH   65536
#define SM_QL   73728
#define SM_RH   81920
#define SM_TOT  (81920 + 64 * 34 * 4)

__global__ void __launch_bounds__(128, 2)
flash_mma(const float* __restrict__ q, const float* __restrict__ k,
          const float* __restrict__ v, float* __restrict__ out)
{
    extern __shared__ __align__(1024) char smem[];
    float* rHs = (float*)(smem + SM_RH);
    const u32 sbase = smem_to_u32(smem);

    const int tid = threadIdx.x;
    const int lane = tid & 31, wid = tid >> 5;
    const int wm = wid * 16;
    const int l4 = lane >> 2;
    const int l2 = lane & 3;
    const int m0 = blockIdx.x << 6;
    const int bh = blockIdx.y;
    const int b = bh >> 4, hd = bh & 15;

    const size_t hoff = (size_t)b * SEQ * 1024 + (size_t)hd * 64;
    const float* qg = q + hoff;
    float*       og = out + hoff;

    const char* gKH = (const char*)(g_KH + (size_t)bh * SEQ * 64);
    const char* gKL = (const char*)(g_KL + (size_t)bh * SEQ * 64);
    const char* gVH = (const char*)(g_VH + (size_t)bh * SEQ * 64);
    const char* gVL = (const char*)(g_VL + (size_t)bh * SEQ * 64);

    // issue cp.async for tile t into buffer bufi
    auto issue_kv = [&](int t, int bufi) {
        const u32 db = sbase + (u32)bufi * KV_BUF;
        const u32 go = (u32)t * 8192;
        #pragma unroll
        for (int j = 0; j < 4; j++) {
            const u32 ch = (u32)((tid + 128 * j) * 16);
            const u32 ds = SWZ(ch);
            cp16(db + ds,          gKH + go + ch);
            cp16(db + 8192 + ds,   gKL + go + ch);
            cp16(db + 16384 + ds,  gVH + go + ch);
            cp16(db + 24576 + ds,  gVL + go + ch);
        }
    };

    issue_kv(0, 0);
    CP_COMMIT();

    // ---- Q convert (scaled, split) + rH table ----
    {
        const int row = tid >> 1, cb = (tid & 1) * 32;
        const float qs = 0.125f * LOG2E;
        const float4* src = (const float4*)(qg + (size_t)(m0 + row) * 1024 + cb);
        #pragma unroll
        for (int f = 0; f < 8; f++) {
            float4 x = src[f];
            u32 h0, l0v, h1, l1v;
            split2(x.x * qs, x.y * qs, h0, l0v);
            split2(x.z * qs, x.w * qs, h1, l1v);
            const u32 bo = (u32)(row * 128 + 2 * (cb + 4 * f));
            const u32 o0 = SWZ(bo), o1 = SWZ(bo + 4);
            *(u32*)(smem + SM_QH + o0) = h0; *(u32*)(smem + SM_QH + o1) = h1;
            *(u32*)(smem + SM_QL + o0) = l0v; *(u32*)(smem + SM_QL + o1) = l1v;
        }
        const float4* rsrc = (const float4*)(g_relH + ((size_t)bh * SEQ + m0 + row) * 32 + (tid & 1) * 16);
        #pragma unroll
        for (int f = 0; f < 4; f++) {
            float4 x = rsrc[f];
            float* d = rHs + row * 34 + (tid & 1) * 16 + 4 * f;
            d[0] = x.x; d[1] = x.y; d[2] = x.z; d[3] = x.w;
        }
    }
    __syncthreads();

    // ---- Q A-fragments (registers, persistent) ----
    u32 aQh[4][4], aQl[4][4];
    {
        const int arow = wm + (lane & 15);
        #pragma unroll
        for (int ks = 0; ks < 4; ks++) {
            const u32 bo = (u32)(arow * 128 + 32 * ks + 16 * (lane >> 4));
            ldsm_x4(aQh[ks][0], aQh[ks][1], aQh[ks][2], aQh[ks][3], sbase + SM_QH + SWZ(bo));
            ldsm_x4(aQl[ks][0], aQl[ks][1], aQl[ks][2], aQl[ks][3], sbase + SM_QL + SWZ(bo));
        }
    }

    // ---- per-thread rel_w regs, row bound, row sums ----
    const int r0g = m0 + wm + l4, r1g = r0g + 8;
    float rw0[8], rw1[8], rowM0, rowM1, lsum0 = 0.f, lsum1 = 0.f;
    {
        const float* w0 = g_relW + ((size_t)bh * SEQ + r0g) * 32;
        const float* w1 = g_relW + ((size_t)bh * SEQ + r1g) * 32;
        #pragma unroll
        for (int j = 0; j < 4; j++) {
            rw0[2 * j]     = w0[8 * j + 2 * l2];
            rw0[2 * j + 1] = w0[8 * j + 2 * l2 + 1];
            rw1[2 * j]     = w1[8 * j + 2 * l2];
            rw1[2 * j + 1] = w1[8 * j + 2 * l2 + 1];
        }
        const float kn = sqrtf(__int_as_float(g_knormi[bh])) * (0.125f * LOG2E);
        float2 ra = g_rowB[(size_t)bh * SEQ + r0g];
        float2 rb = g_rowB[(size_t)bh * SEQ + r1g];
        rowM0 = ra.x + ra.y * kn;
        rowM1 = rb.x + rb.y * kn;
    }

    float o[8][4];
    #pragma unroll
    for (int i = 0; i < 8; i++)
        #pragma unroll
        for (int j = 0; j < 4; j++) o[i][j] = 0.f;

    for (int t = 0; t < 16; t++) {
        if (t < 15) { issue_kv(t + 1, (t + 1) & 1); CP_COMMIT(); }
        if (t < 15) { CP_WAIT(1); } else { CP_WAIT(0); }
        __syncthreads();

        const u32 kb = sbase + (u32)(t & 1) * KV_BUF;

        // ---- S = Qh*Kh + Qh*Kl + Ql*Kh ----
        float s[8][4];
        #pragma unroll
        for (int i = 0; i < 8; i++)
            #pragma unroll
            for (int j = 0; j < 4; j++) s[i][j] = 0.f;

        #pragma unroll
        for (int ks = 0; ks < 4; ks++) {
            u32 bKh[8][2], bKl[8][2];
            const u32 colb = (u32)(32 * ks + 16 * ((lane >> 3) & 1));
            #pragma unroll
            for (int u = 0; u < 4; u++) {
                const u32 bo = (u32)((16 * u + ((lane >> 4) & 1) * 8 + (lane & 7)) * 128) + colb;
                ldsm_x4(bKh[2 * u][0], bKh[2 * u][1], bKh[2 * u + 1][0], bKh[2 * u + 1][1],
                        kb + SWZ(bo));
                ldsm_x4(bKl[2 * u][0], bKl[2 * u][1], bKl[2 * u + 1][0], bKl[2 * u + 1][1],
                        kb + 8192 + SWZ(bo));
            }
            #pragma unroll
            for (int oc = 0; oc < 8; oc++) {
                mma_bf16(s[oc], aQh[ks], bKh[oc][0], bKh[oc][1]);
                mma_bf16(s[oc], aQh[ks], bKl[oc][0], bKl[oc][1]);
                mma_bf16(s[oc], aQl[ks], bKh[oc][0], bKh[oc][1]);
            }
        }

        // ---- softmax (fixed bound) + build P fragments in registers ----
        const int kh0 = 2 * t;
        const float rhA0 = rHs[(wm + l4) * 34 + kh0]     - rowM0;
        const float rhB0 = rHs[(wm + l4) * 34 + kh0 + 1] - rowM0;
        const float rhA1 = rHs[(wm + l4 + 8) * 34 + kh0]     - rowM1;
        const float rhB1 = rHs[(wm + l4 + 8) * 34 + kh0 + 1] - rowM1;

        u32 aPh[4][4], aPl[4][4];
        #pragma unroll
        for (int oc = 0; oc < 8; oc++) {
            const int j = oc & 3;
            const float c0 = (oc < 4) ? rhA0 : rhB0;
            const float c1 = (oc < 4) ? rhA1 : rhB1;
            float p0 = ex2f(s[oc][0] + rw0[2 * j]     + c0);
            float p1 = ex2f(s[oc][1] + rw0[2 * j + 1] + c0);
            float p2 = ex2f(s[oc][2] + rw1[2 * j]     + c1);
            float p3 = ex2f(s[oc][3] + rw1[2 * j + 1] + c1);
            lsum0 += p0 + p1;
            lsum1 += p2 + p3;
            u32 h01, l01, h23, l23;
            split2(p0, p1, h01, l01);
            split2(p2, p3, h23, l23);
            const int kf = oc >> 1, hi = (oc & 1) * 2;
            aPh[kf][hi] = h01; aPh[kf][hi + 1] = h23;
            aPl[kf][hi] = l01; aPl[kf][hi + 1] = l23;
        }

        // ---- O += Ph*Vh + Ph*Vl + Pl*Vh ----
        #pragma unroll
        for (int kf = 0; kf < 4; kf++) {
            u32 bVh[8][2], bVl[8][2];
            const int nb = 16 * kf;
            #pragma unroll
            for (int u = 0; u < 4; u++) {
                const u32 bo = (u32)((nb + ((lane >> 3) & 1) * 8 + (lane & 7)) * 128
                                     + 32 * u + 16 * ((lane >> 4) & 1));
                ldsm_x4_t(bVh[2 * u][0], bVh[2 * u][1], bVh[2 * u + 1][0], bVh[2 * u + 1][1],
                          kb + 16384 + SWZ(bo));
                ldsm_x4_t(bVl[2 * u][0], bVl[2 * u][1], bVl[2 * u + 1][0], bVl[2 * u + 1][1],
                          kb + 24576 + SWZ(bo));
            }
            #pragma unroll
            for (int du = 0; du < 8; du++) {
                mma_bf16(o[du], aPh[kf], bVh[du][0], bVh[du][1]);
                mma_bf16(o[du], aPh[kf], bVl[du][0], bVl[du][1]);
                mma_bf16(o[du], aPl[kf], bVh[du][0], bVh[du][1]);
            }
        }
        __syncthreads();   // release buffer (t&1) before next iteration's issue
    }

    // ---- finalize: reduce row sums over 4-lane groups, normalize, store ----
    lsum0 += __shfl_xor_sync(0xffffffffu, lsum0, 1);
    lsum0 += __shfl_xor_sync(0xffffffffu, lsum0, 2);
    lsum1 += __shfl_xor_sync(0xffffffffu, lsum1, 1);
    lsum1 += __shfl_xor_sync(0xffffffffu, lsum1, 2);
    const float inv0 = __fdividef(1.0f, lsum0);
    const float inv1 = __fdividef(1.0f, lsum1);

    float* op0 = og + (size_t)r0g * 1024;
    float* op1 = og + (size_t)r1g * 1024;
    #pragma unroll
    for (int du = 0; du < 8; du++) {
        const int d = 8 * du + 2 * l2;
        *(float2*)(op0 + d) = make_float2(o[du][0] * inv0, o[du][1] * inv0);
        *(float2*)(op1 + d) = make_float2(o[du][2] * inv1, o[du][3] * inv1);
    }
}

extern "C" void kernel_launch(void* const* d_in, const int* in_sizes, int n_in,
                              void* d_out, int out_size)
{
    const float* q   = (const float*)d_in[0];
    const float* k   = (const float*)d_in[1];
    const float* v   = (const float*)d_in[2];
    const float* rph = (const float*)d_in[3];
    const float* rpw = (const float*)d_in[4];
    float* out = (float*)d_out;

    dim3 cg(16, 64);
    kv_convert<<<cg, 128>>>(k, v);

    dim3 rg(32, 64);
    rel_kernel<<<rg, 256>>>(q, rph, rpw);

    cudaFuncSetAttribute(flash_mma, cudaFuncAttributeMaxDynamicSharedMemorySize, SM_TOT);
    dim3 grid(SEQ / 64, NBH);
    flash_mma<<<grid, 128, SM_TOT>>>(q, k, v, out);
}

// round 16
// speedup vs baseline: 2.8094x; 1.0665x over previous
#include <cuda_runtime.h>
#include <cuda_bf16.h>

typedef unsigned long long ull;
typedef unsigned int u32;

#define SEQ   1024
#define NBH   64
#define LOG2E 1.4426950408889634f

// per-head max ||k||^2 as float bits (atomicMax; zero-init; idempotent across replays)
__device__ int g_knormi[NBH];
// pre-converted bf16 hi/lo K and V: [bh][n][c] linear, 128B rows
__device__ __align__(16) __nv_bfloat16 g_KH[(size_t)NBH * SEQ * 64];
__device__ __align__(16) __nv_bfloat16 g_KL[(size_t)NBH * SEQ * 64];
__device__ __align__(16) __nv_bfloat16 g_VH[(size_t)NBH * SEQ * 64];
__device__ __align__(16) __nv_bfloat16 g_VL[(size_t)NBH * SEQ * 64];
// pre-converted bf16 hi/lo rel tables, scaled by 8 (cancels Q's 0.125)
__device__ __align__(16) __nv_bfloat16 g_RphH[63 * 64];
__device__ __align__(16) __nv_bfloat16 g_RphL[63 * 64];
__device__ __align__(16) __nv_bfloat16 g_RpwH[64 * 64];   // row 63 zeroed
__device__ __align__(16) __nv_bfloat16 g_RpwL[64 * 64];

// ---------------- helpers ----------------
__device__ __forceinline__ float ex2f(float x) {
    float r; asm("ex2.approx.f32 %0, %1;" : "=f"(r) : "f"(x)); return r;
}
__device__ __forceinline__ u32 smem_to_u32(const void* p) {
    u32 a;
    asm("{ .reg .u64 t; cvta.to.shared.u64 t, %1; cvt.u32.u64 %0, t; }" : "=r"(a) : "l"(p));
    return a;
}
#define SWZ(off) ((off) ^ (((off) >> 3) & 0x70))

__device__ __forceinline__ void ldsm_x4(u32& r0, u32& r1, u32& r2, u32& r3, u32 a) {
    asm volatile("ldmatrix.sync.aligned.m8n8.x4.shared.b16 {%0,%1,%2,%3}, [%4];"
                 : "=r"(r0), "=r"(r1), "=r"(r2), "=r"(r3) : "r"(a));
}
__device__ __forceinline__ void ldsm_x4_t(u32& r0, u32& r1, u32& r2, u32& r3, u32 a) {
    asm volatile("ldmatrix.sync.aligned.m8n8.x4.trans.shared.b16 {%0,%1,%2,%3}, [%4];"
                 : "=r"(r0), "=r"(r1), "=r"(r2), "=r"(r3) : "r"(a));
}
__device__ __forceinline__ void mma_bf16(float* c, const u32* a, u32 b0, u32 b1) {
    asm volatile("mma.sync.aligned.m16n8k16.row.col.f32.bf16.bf16.f32 "
                 "{%0,%1,%2,%3}, {%4,%5,%6,%7}, {%8,%9}, {%0,%1,%2,%3};"
                 : "+f"(c[0]), "+f"(c[1]), "+f"(c[2]), "+f"(c[3])
                 : "r"(a[0]), "r"(a[1]), "r"(a[2]), "r"(a[3]), "r"(b0), "r"(b1));
}
__device__ __forceinline__ void split2(float a, float b, u32& hi, u32& lo) {
    __nv_bfloat162 h = __floats2bfloat162_rn(a, b);
    hi = *(u32*)&h;
    float ra = a - __low2float(h);
    float rb = b - __high2float(h);
    __nv_bfloat162 l = __floats2bfloat162_rn(ra, rb);
    lo = *(u32*)&l;
}
__device__ __forceinline__ void cp16(u32 dst, const void* src) {
    asm volatile("cp.async.cg.shared.global [%0], [%1], 16;" :: "r"(dst), "l"(src) : "memory");
}
#define CP_COMMIT() asm volatile("cp.async.commit_group;" ::: "memory")
#define CP_WAIT(n)  asm volatile("cp.async.wait_group %0;" :: "n"(n) : "memory")

// ---------- kernel C: K/V pre-convert to bf16 hi/lo + per-head knorm ----------
// grid (8, 64), 128 threads: one full row per thread.
__global__ void __launch_bounds__(128) kv_convert(const float* __restrict__ k,
                                                  const float* __restrict__ v)
{
    const int tid = threadIdx.x;
    const int bh = blockIdx.y;
    const int b = bh >> 4, hd = bh & 15;
    const int r = blockIdx.x * 128 + tid;
    const size_t hoff = (size_t)b * SEQ * 1024 + (size_t)hd * 64;

    const float4* ks = (const float4*)(k + hoff + (size_t)r * 1024);
    const float4* vs = (const float4*)(v + hoff + (size_t)r * 1024);
    const size_t eb = ((size_t)bh * SEQ + r) * 32;   // u32 index
    u32* dKH = (u32*)g_KH + eb;
    u32* dKL = (u32*)g_KL + eb;
    u32* dVH = (u32*)g_VH + eb;
    u32* dVL = (u32*)g_VL + eb;

    float ksum = 0.f;
    #pragma unroll
    for (int f = 0; f < 16; f++) {
        float4 x = ks[f];
        ksum += x.x * x.x + x.y * x.y + x.z * x.z + x.w * x.w;
        u32 h0, l0, h1, l1;
        split2(x.x, x.y, h0, l0);
        split2(x.z, x.w, h1, l1);
        dKH[2 * f] = h0; dKH[2 * f + 1] = h1;
        dKL[2 * f] = l0; dKL[2 * f + 1] = l1;
        float4 y = vs[f];
        split2(y.x, y.y, h0, l0);
        split2(y.z, y.w, h1, l1);
        dVH[2 * f] = h0; dVH[2 * f + 1] = h1;
        dVL[2 * f] = l0; dVL[2 * f + 1] = l1;
    }
    #pragma unroll
    for (int m = 1; m <= 16; m <<= 1)
        ksum = fmaxf(ksum, __shfl_xor_sync(0xffffffffu, ksum, m));
    if ((tid & 31) == 0) atomicMax(&g_knormi[bh], __float_as_int(ksum));
}

// ---------- kernel R: rel table convert (x8 scale, bf16 hi/lo) ----------
__global__ void __launch_bounds__(128) rel_convert(const float* __restrict__ rph,
                                                   const float* __restrict__ rpw)
{
    const int tid = threadIdx.x;
    for (int i = tid; i < 63 * 32; i += 128) {   // i indexes float2
        float2 x = ((const float2*)rph)[i];
        u32 h, l;
        split2(x.x * 8.f, x.y * 8.f, h, l);
        ((u32*)g_RphH)[i] = h; ((u32*)g_RphL)[i] = l;
        float2 y = ((const float2*)rpw)[i];
        split2(y.x * 8.f, y.y * 8.f, h, l);
        ((u32*)g_RpwH)[i] = h; ((u32*)g_RpwL)[i] = l;
    }
    if (tid < 32) {   // zero pad row 63 of Rpw
        ((u32*)g_RpwH)[63 * 32 + tid] = 0;
        ((u32*)g_RpwL)[63 * 32 + tid] = 0;
    }
}

// ---------- kernel B: mma.sync bf16 flash attention -------------------------
// 128 threads / 4 warps, BM=64, BN=64, bf16 3-term splits, fixed-bound softmax.
// rel_h/rel_w computed in prologue via MMA (Q frags x staged R tiles).
#define KV_BUF  32768       // per buffer: KH,KL,VH,VL 8KB each
#define SM_QH   65536
#define SM_QL   73728
#define SM_RH   81920       // rHs: 64 x 34 f32 = 8704
#define SM_QN   (SM_RH + 8704)   // 64 f32 row |q|
#define SM_TOT  (SM_QN + 256)

__global__ void __launch_bounds__(128, 2)
flash_mma(const float* __restrict__ q, float* __restrict__ out)
{
    extern __shared__ __align__(1024) char smem[];
    float* rHs = (float*)(smem + SM_RH);
    float* sQn = (float*)(smem + SM_QN);
    float* sG  = (float*)(smem + KV_BUF);       // relW results, stride 66 (prologue only)
    const u32 sbase = smem_to_u32(smem);

    const int tid = threadIdx.x;
    const int lane = tid & 31, wid = tid >> 5;
    const int wm = wid * 16;
    const int l4 = lane >> 2;
    const int l2 = lane & 3;
    const int m0 = blockIdx.x << 6;
    const int bh = blockIdx.y;
    const int b = bh >> 4, hd = bh & 15;
    const int ha = m0 >> 5;

    const size_t hoff = (size_t)b * SEQ * 1024 + (size_t)hd * 64;
    const float* qg = q + hoff;
    float*       og = out + hoff;

    const char* gKH = (const char*)(g_KH + (size_t)bh * SEQ * 64);
    const char* gKL = (const char*)(g_KL + (size_t)bh * SEQ * 64);
    const char* gVH = (const char*)(g_VH + (size_t)bh * SEQ * 64);
    const char* gVL = (const char*)(g_VL + (size_t)bh * SEQ * 64);

    auto issue_kv = [&](int t, int bufi) {
        const u32 db = sbase + (u32)bufi * KV_BUF;
        const u32 go = (u32)t * 8192;
        #pragma unroll
        for (int j = 0; j < 4; j++) {
            const u32 ch = (u32)((tid + 128 * j) * 16);
            const u32 ds = SWZ(ch);
            cp16(db + ds,          gKH + go + ch);
            cp16(db + 8192 + ds,   gKL + go + ch);
            cp16(db + 16384 + ds,  gVH + go + ch);
            cp16(db + 24576 + ds,  gVL + go + ch);
        }
    };

    issue_kv(0, 0);
    CP_COMMIT();

    // ---- stage R tiles into buf1: [RhaH|RhaL|RhbH|RhbL|RwH|RwL] = 32KB ----
    {
        const u32 b1 = sbase + KV_BUF;
        {   // Rh: 32 rows x 4 regions; reg: 0=aH 1=aL 2=bH 3=bL
            const int n = tid & 31, reg = tid >> 5;
            const int hsel = reg >> 1, lo = reg & 1;
            const char* src = (const char*)(lo ? g_RphL : g_RphH)
                              + (size_t)(ha + hsel + 31 - n) * 128;
            const u32 dreg = b1 + (u32)reg * 4096;
            #pragma unroll
            for (int j = 0; j < 8; j++)
                cp16(dreg + SWZ((u32)(n * 128 + 16 * j)), src + 16 * j);
        }
        {   // Rw: 64 rows x 2 regions (H at +16384, L at +24576)
            const int n = tid & 63, lo = tid >> 6;
            const char* src = (const char*)(lo ? g_RpwL : g_RpwH) + (size_t)n * 128;
            const u32 dreg = b1 + 16384u + (u32)lo * 8192;
            #pragma unroll
            for (int j = 0; j < 8; j++)
                cp16(dreg + SWZ((u32)(n * 128 + 16 * j)), src + 16 * j);
        }
        CP_COMMIT();
    }

    // ---- Q convert (scaled, split) + row |q| ----
    {
        const int row = tid >> 1, cb = (tid & 1) * 32;
        const float qs = 0.125f * LOG2E;
        const float4* src = (const float4*)(qg + (size_t)(m0 + row) * 1024 + cb);
        float qn = 0.f;
        #pragma unroll
        for (int f = 0; f < 8; f++) {
            float4 x = src[f];
            qn += x.x * x.x + x.y * x.y + x.z * x.z + x.w * x.w;
            u32 h0, l0v, h1, l1v;
            split2(x.x * qs, x.y * qs, h0, l0v);
            split2(x.z * qs, x.w * qs, h1, l1v);
            const u32 bo = (u32)(row * 128 + 2 * (cb + 4 * f));
            const u32 o0 = SWZ(bo), o1 = SWZ(bo + 4);
            *(u32*)(smem + SM_QH + o0) = h0; *(u32*)(smem + SM_QH + o1) = h1;
            *(u32*)(smem + SM_QL + o0) = l0v; *(u32*)(smem + SM_QL + o1) = l1v;
        }
        qn += __shfl_xor_sync(0xffffffffu, qn, 1);
        if (!(tid & 1)) sQn[row] = sqrtf(qn);
    }
    CP_WAIT(0);
    __syncthreads();

    // ---- Q A-fragments (registers, persistent) ----
    u32 aQh[4][4], aQl[4][4];
    {
        const int arow = wm + (lane & 15);
        #pragma unroll
        for (int ks = 0; ks < 4; ks++) {
            const u32 bo = (u32)(arow * 128 + 32 * ks + 16 * (lane >> 4));
            ldsm_x4(aQh[ks][0], aQh[ks][1], aQh[ks][2], aQh[ks][3], sbase + SM_QH + SWZ(bo));
            ldsm_x4(aQl[ks][0], aQl[ks][1], aQl[ks][2], aQl[ks][3], sbase + SM_QL + SWZ(bo));
        }
    }

    // ---- rel GEMMs: relH (own h-group, N=32) and relW (N=64) ----
    float ch[4][4], cw[8][4];
    #pragma unroll
    for (int i = 0; i < 4; i++)
        #pragma unroll
        for (int j = 0; j < 4; j++) ch[i][j] = 0.f;
    #pragma unroll
    for (int i = 0; i < 8; i++)
        #pragma unroll
        for (int j = 0; j < 4; j++) cw[i][j] = 0.f;

    {
        const u32 rhH = sbase + KV_BUF + ((u32)(wid >> 1)) * 8192;
        const u32 rhL = rhH + 4096;
        const u32 rwH = sbase + KV_BUF + 16384;
        const u32 rwL = rwH + 8192;
        #pragma unroll
        for (int ks = 0; ks < 4; ks++) {
            const u32 colb = (u32)(32 * ks + 16 * ((lane >> 3) & 1));
            // relH: 32 rows -> u < 2
            u32 hh[4][2], hl[4][2];
            #pragma unroll
            for (int u = 0; u < 2; u++) {
                const u32 bo = (u32)((16 * u + ((lane >> 4) & 1) * 8 + (lane & 7)) * 128) + colb;
                ldsm_x4(hh[2 * u][0], hh[2 * u][1], hh[2 * u + 1][0], hh[2 * u + 1][1], rhH + SWZ(bo));
                ldsm_x4(hl[2 * u][0], hl[2 * u][1], hl[2 * u + 1][0], hl[2 * u + 1][1], rhL + SWZ(bo));
            }
            #pragma unroll
            for (int oc = 0; oc < 4; oc++) {
                mma_bf16(ch[oc], aQh[ks], hh[oc][0], hh[oc][1]);
                mma_bf16(ch[oc], aQh[ks], hl[oc][0], hl[oc][1]);
                mma_bf16(ch[oc], aQl[ks], hh[oc][0], hh[oc][1]);
            }
            // relW: 64 rows -> u < 4
            u32 wh[8][2], wl[8][2];
            #pragma unroll
            for (int u = 0; u < 4; u++) {
                const u32 bo = (u32)((16 * u + ((lane >> 4) & 1) * 8 + (lane & 7)) * 128) + colb;
                ldsm_x4(wh[2 * u][0], wh[2 * u][1], wh[2 * u + 1][0], wh[2 * u + 1][1], rwH + SWZ(bo));
                ldsm_x4(wl[2 * u][0], wl[2 * u][1], wl[2 * u + 1][0], wl[2 * u + 1][1], rwL + SWZ(bo));
            }
            #pragma unroll
            for (int oc = 0; oc < 8; oc++) {
                mma_bf16(cw[oc], aQh[ks], wh[oc][0], wh[oc][1]);
                mma_bf16(cw[oc], aQh[ks], wl[oc][0], wl[oc][1]);
                mma_bf16(cw[oc], aQl[ks], wh[oc][0], wh[oc][1]);
            }
        }
    }
    __syncthreads();   // all ldsm of buf1 done; now overwrite with G

    // ---- store relH -> rHs (stride 34), relW -> sG (stride 66) ----
    {
        const int r0 = wm + l4, r1 = r0 + 8;
        #pragma unroll
        for (int oc = 0; oc < 4; oc++) {
            const int c = 8 * oc + 2 * l2;
            rHs[r0 * 34 + c] = ch[oc][0]; rHs[r0 * 34 + c + 1] = ch[oc][1];
            rHs[r1 * 34 + c] = ch[oc][2]; rHs[r1 * 34 + c + 1] = ch[oc][3];
        }
        #pragma unroll
        for (int oc = 0; oc < 8; oc++) {
            const int c = 8 * oc + 2 * l2;
            sG[r0 * 66 + c] = cw[oc][0]; sG[r0 * 66 + c + 1] = cw[oc][1];
            sG[r1 * 66 + c] = cw[oc][2]; sG[r1 * 66 + c + 1] = cw[oc][3];
        }
    }
    __syncthreads();

    // ---- per-thread rel_w regs + fixed row bounds ----
    const int r0loc = wm + l4, r1loc = r0loc + 8;
    const int r0g = m0 + r0loc, r1g = m0 + r1loc;
    const int w0 = r0loc & 31, w1 = r1loc & 31;
    float rw0[8], rw1[8], rowM0, rowM1, lsum0 = 0.f, lsum1 = 0.f;
    {
        const float* G0 = sG + r0loc * 66;
        const float* G1 = sG + r1loc * 66;
        #pragma unroll
        for (int j = 0; j < 4; j++) {
            const int kw = 8 * j + 2 * l2;
            rw0[2 * j]     = G0[w0 + 31 - kw];
            rw0[2 * j + 1] = G0[w0 + 30 - kw];
            rw1[2 * j]     = G1[w1 + 31 - kw];
            rw1[2 * j + 1] = G1[w1 + 30 - kw];
        }
        const float kn = sqrtf(__int_as_float(g_knormi[bh])) * (0.125f * LOG2E);
        float mh0 = -3.0e38f, mh1 = -3.0e38f, mw0 = -3.0e38f, mw1 = -3.0e38f;
        #pragma unroll 8
        for (int j = 0; j < 32; j++) {
            mh0 = fmaxf(mh0, rHs[r0loc * 34 + j]);
            mh1 = fmaxf(mh1, rHs[r1loc * 34 + j]);
            mw0 = fmaxf(mw0, G0[w0 + j]);
            mw1 = fmaxf(mw1, G1[w1 + j]);
        }
        rowM0 = mh0 + mw0 + sQn[r0loc] * kn;
        rowM1 = mh1 + mw1 + sQn[r1loc] * kn;
    }
    __syncthreads();   // done reading sG (buf1) before loop issues into it

    float o[8][4];
    #pragma unroll
    for (int i = 0; i < 8; i++)
        #pragma unroll
        for (int j = 0; j < 4; j++) o[i][j] = 0.f;

    for (int t = 0; t < 16; t++) {
        if (t < 15) { issue_kv(t + 1, (t + 1) & 1); CP_COMMIT(); }
        if (t < 15) { CP_WAIT(1); } else { CP_WAIT(0); }
        __syncthreads();

        const u32 kb = sbase + (u32)(t & 1) * KV_BUF;

        // ---- S = Qh*Kh + Qh*Kl + Ql*Kh ----
        float s[8][4];
        #pragma unroll
        for (int i = 0; i < 8; i++)
            #pragma unroll
            for (int j = 0; j < 4; j++) s[i][j] = 0.f;

        #pragma unroll
        for (int ks = 0; ks < 4; ks++) {
            u32 bKh[8][2], bKl[8][2];
            const u32 colb = (u32)(32 * ks + 16 * ((lane >> 3) & 1));
            #pragma unroll
            for (int u = 0; u < 4; u++) {
                const u32 bo = (u32)((16 * u + ((lane >> 4) & 1) * 8 + (lane & 7)) * 128) + colb;
                ldsm_x4(bKh[2 * u][0], bKh[2 * u][1], bKh[2 * u + 1][0], bKh[2 * u + 1][1],
                        kb + SWZ(bo));
                ldsm_x4(bKl[2 * u][0], bKl[2 * u][1], bKl[2 * u + 1][0], bKl[2 * u + 1][1],
                        kb + 8192 + SWZ(bo));
            }
            #pragma unroll
            for (int oc = 0; oc < 8; oc++) {
                mma_bf16(s[oc], aQh[ks], bKh[oc][0], bKh[oc][1]);
                mma_bf16(s[oc], aQh[ks], bKl[oc][0], bKl[oc][1]);
                mma_bf16(s[oc], aQl[ks], bKh[oc][0], bKh[oc][1]);
            }
        }

        // ---- softmax (fixed bound) + build P fragments in registers ----
        const int kh0 = 2 * t;
        const float rhA0 = rHs[r0loc * 34 + kh0]     - rowM0;
        const float rhB0 = rHs[r0loc * 34 + kh0 + 1] - rowM0;
        const float rhA1 = rHs[r1loc * 34 + kh0]     - rowM1;
        const float rhB1 = rHs[r1loc * 34 + kh0 + 1] - rowM1;

        u32 aPh[4][4], aPl[4][4];
        #pragma unroll
        for (int oc = 0; oc < 8; oc++) {
            const int j = oc & 3;
            const float c0 = (oc < 4) ? rhA0 : rhB0;
            const float c1 = (oc < 4) ? rhA1 : rhB1;
            float p0 = ex2f(s[oc][0] + rw0[2 * j]     + c0);
            float p1 = ex2f(s[oc][1] + rw0[2 * j + 1] + c0);
            float p2 = ex2f(s[oc][2] + rw1[2 * j]     + c1);
            float p3 = ex2f(s[oc][3] + rw1[2 * j + 1] + c1);
            lsum0 += p0 + p1;
            lsum1 += p2 + p3;
            u32 h01, l01, h23, l23;
            split2(p0, p1, h01, l01);
            split2(p2, p3, h23, l23);
            const int kf = oc >> 1, hi = (oc & 1) * 2;
            aPh[kf][hi] = h01; aPh[kf][hi + 1] = h23;
            aPl[kf][hi] = l01; aPl[kf][hi + 1] = l23;
        }

        // ---- O += Ph*Vh + Ph*Vl + Pl*Vh ----
        #pragma unroll
        for (int kf = 0; kf < 4; kf++) {
            u32 bVh[8][2], bVl[8][2];
            const int nb = 16 * kf;
            #pragma unroll
            for (int u = 0; u < 4; u++) {
                const u32 bo = (u32)((nb + ((lane >> 3) & 1) * 8 + (lane & 7)) * 128
                                     + 32 * u + 16 * ((lane >> 4) & 1));
                ldsm_x4_t(bVh[2 * u][0], bVh[2 * u][1], bVh[2 * u + 1][0], bVh[2 * u + 1][1],
                          kb + 16384 + SWZ(bo));
                ldsm_x4_t(bVl[2 * u][0], bVl[2 * u][1], bVl[2 * u + 1][0], bVl[2 * u + 1][1],
                          kb + 24576 + SWZ(bo));
            }
            #pragma unroll
            for (int du = 0; du < 8; du++) {
                mma_bf16(o[du], aPh[kf], bVh[du][0], bVh[du][1]);
                mma_bf16(o[du], aPh[kf], bVl[du][0], bVl[du][1]);
                mma_bf16(o[du], aPl[kf], bVh[du][0], bVh[du][1]);
            }
        }
        __syncthreads();   // release read buffer before next issue overwrites it
    }

    // ---- finalize ----
    lsum0 += __shfl_xor_sync(0xffffffffu, lsum0, 1);
    lsum0 += __shfl_xor_sync(0xffffffffu, lsum0, 2);
    lsum1 += __shfl_xor_sync(0xffffffffu, lsum1, 1);
    lsum1 += __shfl_xor_sync(0xffffffffu, lsum1, 2);
    const float inv0 = __fdividef(1.0f, lsum0);
    const float inv1 = __fdividef(1.0f, lsum1);

    float* op0 = og + (size_t)r0g * 1024;
    float* op1 = og + (size_t)r1g * 1024;
    #pragma unroll
    for (int du = 0; du < 8; du++) {
        const int d = 8 * du + 2 * l2;
        *(float2*)(op0 + d) = make_float2(o[du][0] * inv0, o[du][1] * inv0);
        *(float2*)(op1 + d) = make_float2(o[du][2] * inv1, o[du][3] * inv1);
    }
}

extern "C" void kernel_launch(void* const* d_in, const int* in_sizes, int n_in,
                              void* d_out, int out_size)
{
    const float* q   = (const float*)d_in[0];
    const float* k   = (const float*)d_in[1];
    const float* v   = (const float*)d_in[2];
    const float* rph = (const float*)d_in[3];
    const float* rpw = (const float*)d_in[4];
    float* out = (float*)d_out;

    dim3 cg(8, 64);
    kv_convert<<<cg, 128>>>(k, v);
    rel_convert<<<1, 128>>>(rph, rpw);

    cudaFuncSetAttribute(flash_mma, cudaFuncAttributeMaxDynamicSharedMemorySize, SM_TOT);
    dim3 grid(SEQ / 64, NBH);
    flash_mma<<<grid, 128, SM_TOT>>>(q, out);
}